// round 3
// baseline (speedup 1.0000x reference)
#include <cuda_runtime.h>
#include <math.h>

#define T_STEPS 32
#define N_BATCH 16
#define D_DIM   256
#define A_DIM   256
#define F1_DIM  512
#define F2_DIM  256
#define BK 16

// Scratch (allocation-free rule: __device__ globals)
__device__ float g_s2[T_STEPS * N_BATCH * D_DIM];    // [T,N,D]   512KB
__device__ float g_h1[T_STEPS * N_BATCH * F1_DIM];   // [T,N,F1]  1MB
__device__ float g_h2[T_STEPS * N_BATCH * F2_DIM];   // [T,N,F2]  512KB
__device__ float g_part[1 * 1024 * 1024];            // split-K partials, 4MB

// ---------------------------------------------------------------------------
// K1: fused SDC-linear + exp-filter + LIF + synapse-filter + pool + s2-LIF.
// block = (n,d) pair (4096 blocks), thread = a (256 threads).
// Main loop: 1 STS per t (no shuffles). Reduction: t-parallel across warps.
// ---------------------------------------------------------------------------
__global__ void __launch_bounds__(256) k_snn_core(
    const float* __restrict__ x,      // [T,N,2,D]
    const float* __restrict__ W_sdc,  // [2,A]
    const float* __restrict__ b_sdc,  // [A]
    const float* __restrict__ w_syn,  // [1]
    const float* __restrict__ W_pool, // [A,1]
    const float* __restrict__ b_pool) // [1]
{
    const int a    = threadIdx.x;
    const int nd   = blockIdx.x;
    const int n    = nd >> 8;   // D = 256
    const int d    = nd & 255;
    const int lane = a & 31;
    const int warp = a >> 5;

    __shared__ float xs[T_STEPS][2];
    __shared__ float sh[T_STEPS][A_DIM];   // 32KB: syn*wp per (t,a)
    __shared__ float zsh[T_STEPS];

    if (a < 64) {
        const int t = a >> 1, c = a & 1;
        xs[t][c] = x[((t * N_BATCH + n) * 2 + c) * D_DIM + d];
    }

    const float w0 = W_sdc[a];
    const float w1 = W_sdc[A_DIM + a];
    const float ba = b_sdc[a];
    const float wp = W_pool[a];
    const float dsyn = 1.0f - 1.0f / (1.0f + expf(-w_syn[0]));
    const float bp = b_pool[0];

    __syncthreads();

    float i_s = 0.0f, v = 0.0f, syn = 0.0f;
    #pragma unroll
    for (int t = 0; t < T_STEPS; ++t) {
        const float h = fmaf(xs[t][0], w0, fmaf(xs[t][1], w1, ba));
        i_s = fmaf(i_s, 0.5f, h);                     // exp_filter, tau=2
        v = fmaf(i_s - v, 0.5f, v);                   // LIF tau=2
        const float s1 = (v >= 1.0f) ? 1.0f : 0.0f;
        v = (s1 != 0.0f) ? 0.0f : v;
        syn = fmaf(syn, dsyn, s1);                    // synapse filter
        sh[t][a] = syn * wp;
    }
    __syncthreads();

    // t-parallel pooled reduction: warp w handles t = w, w+8, w+16, w+24
    #pragma unroll
    for (int tt = warp; tt < T_STEPS; tt += 8) {
        float val = 0.0f;
        #pragma unroll
        for (int i = 0; i < 8; ++i) val += sh[tt][lane + 32 * i];
        #pragma unroll
        for (int off = 16; off; off >>= 1)
            val += __shfl_down_sync(0xffffffffu, val, off);
        if (lane == 0) zsh[tt] = val + bp;
    }
    __syncthreads();

    if (warp == 0) {
        const float z = zsh[lane];   // lane == t
        float v2 = 0.0f, s_mine = 0.0f;
        #pragma unroll
        for (int t = 0; t < T_STEPS; ++t) {
            const float zt = __shfl_sync(0xffffffffu, z, t);
            v2 = fmaf(zt - v2, 0.5f, v2);
            const float s = (v2 >= 1.0f) ? 1.0f : 0.0f;
            v2 = (s != 0.0f) ? 0.0f : v2;
            if (lane == t) s_mine = s;
        }
        g_s2[(lane * N_BATCH + n) * D_DIM + d] = s_mine;
    }
}

// ---------------------------------------------------------------------------
// Split-K register-tiled SGEMM: P[s][M][N] partial = A[:,ks..ks+Kc] @ B slice.
// Tile 32(M) x 64(N), BK=16, 128 threads, 4x4 micro-tile. Deterministic.
// ---------------------------------------------------------------------------
__global__ void __launch_bounds__(128) k_gemm_splitk(
    const float* __restrict__ A, const float* __restrict__ B,
    float* __restrict__ P, int M, int K, int N, int Kc)
{
    __shared__ float As[BK][32];   // [k][m]
    __shared__ float Bs[BK][64];   // [k][n]
    const int tid = threadIdx.x;
    const int tx  = tid & 15;
    const int ty  = tid >> 4;
    const int row0 = blockIdx.y * 32;
    const int col0 = blockIdx.x * 64;
    const int s    = blockIdx.z;
    const int kbeg = s * Kc;

    const int alr = tid >> 2;
    const int alk = (tid & 3) << 2;
    const int brr = tid >> 4;
    const int bcc = (tid & 15) << 2;

    float acc[4][4] = {};

    for (int k0 = kbeg; k0 < kbeg + Kc; k0 += BK) {
        const float4 av  = *(const float4*)(A + (row0 + alr) * K + k0 + alk);
        const float4 bv0 = *(const float4*)(B + (k0 + brr    ) * N + col0 + bcc);
        const float4 bv1 = *(const float4*)(B + (k0 + brr + 8) * N + col0 + bcc);
        As[alk + 0][alr] = av.x;
        As[alk + 1][alr] = av.y;
        As[alk + 2][alr] = av.z;
        As[alk + 3][alr] = av.w;
        *(float4*)(&Bs[brr][bcc])     = bv0;
        *(float4*)(&Bs[brr + 8][bcc]) = bv1;
        __syncthreads();
        #pragma unroll
        for (int kk = 0; kk < BK; ++kk) {
            const float4 a = *(const float4*)(&As[kk][ty << 2]);
            const float4 b = *(const float4*)(&Bs[kk][tx << 2]);
            acc[0][0] = fmaf(a.x, b.x, acc[0][0]);
            acc[0][1] = fmaf(a.x, b.y, acc[0][1]);
            acc[0][2] = fmaf(a.x, b.z, acc[0][2]);
            acc[0][3] = fmaf(a.x, b.w, acc[0][3]);
            acc[1][0] = fmaf(a.y, b.x, acc[1][0]);
            acc[1][1] = fmaf(a.y, b.y, acc[1][1]);
            acc[1][2] = fmaf(a.y, b.z, acc[1][2]);
            acc[1][3] = fmaf(a.y, b.w, acc[1][3]);
            acc[2][0] = fmaf(a.z, b.x, acc[2][0]);
            acc[2][1] = fmaf(a.z, b.y, acc[2][1]);
            acc[2][2] = fmaf(a.z, b.z, acc[2][2]);
            acc[2][3] = fmaf(a.z, b.w, acc[2][3]);
            acc[3][0] = fmaf(a.w, b.x, acc[3][0]);
            acc[3][1] = fmaf(a.w, b.y, acc[3][1]);
            acc[3][2] = fmaf(a.w, b.z, acc[3][2]);
            acc[3][3] = fmaf(a.w, b.w, acc[3][3]);
        }
        __syncthreads();
    }

    float* Pout = P + s * M * N;
    #pragma unroll
    for (int i = 0; i < 4; ++i) {
        float4 o;
        o.x = acc[i][0]; o.y = acc[i][1]; o.z = acc[i][2]; o.w = acc[i][3];
        *(float4*)(Pout + (row0 + (ty << 2) + i) * N + col0 + (tx << 2)) = o;
    }
}

// ---------------------------------------------------------------------------
// Fused split-K reduce + bias + LIF scan over t.
// P[s][T*N_BATCH][F] partials -> out[T*N_BATCH][F] spikes.
// thread j = (nb, f); fixed reduction order => deterministic.
// ---------------------------------------------------------------------------
template<int S>
__global__ void k_reduce_lif(const float* __restrict__ P,
                             const float* __restrict__ bias,
                             float* __restrict__ out, int F)
{
    const int j = blockIdx.x * blockDim.x + threadIdx.x;
    const int nb = j / F;
    const int f  = j % F;
    const int MN = T_STEPS * N_BATCH * F;
    const float b = bias[f];
    float v = 0.0f;
    #pragma unroll 4
    for (int t = 0; t < T_STEPS; ++t) {
        const int m = t * N_BATCH + nb;
        float val = b;
        #pragma unroll
        for (int s = 0; s < S; ++s) val += P[s * MN + m * F + f];
        v = fmaf(val - v, 0.5f, v);
        const float sp = (v >= 1.0f) ? 1.0f : 0.0f;
        out[m * F + f] = sp;
        v = (sp != 0.0f) ? 0.0f : v;
    }
}

// ---------------------------------------------------------------------------
// Head: o[t,n] = h2[t,n,:] . W_out + b_out ; out[t,n] = cumsum_t o
// ---------------------------------------------------------------------------
__global__ void __launch_bounds__(256) k_head(
    const float* __restrict__ W_out, const float* __restrict__ b_out,
    float* __restrict__ out)
{
    const int n = blockIdx.x;
    const int g = threadIdx.x;
    const int lane = g & 31;
    const int warp = g >> 5;
    const float w  = W_out[g];
    const float bo = b_out[0];
    __shared__ float sh[T_STEPS][8];

    #pragma unroll 4
    for (int t = 0; t < T_STEPS; ++t) {
        float val = g_h2[(t * N_BATCH + n) * F2_DIM + g] * w;
        #pragma unroll
        for (int off = 16; off; off >>= 1)
            val += __shfl_down_sync(0xffffffffu, val, off);
        if (lane == 0) sh[t][warp] = val;
    }
    __syncthreads();
    if (warp == 0) {
        float z = bo;
        #pragma unroll
        for (int w8 = 0; w8 < 8; ++w8) z += sh[lane][w8];
        float acc = 0.0f, mine = 0.0f;
        #pragma unroll
        for (int t = 0; t < T_STEPS; ++t) {
            acc += __shfl_sync(0xffffffffu, z, t);
            if (lane == t) mine = acc;
        }
        out[lane * N_BATCH + n] = mine;
    }
}

extern "C" void kernel_launch(void* const* d_in, const int* in_sizes, int n_in,
                              void* d_out, int out_size)
{
    const float* x      = (const float*)d_in[0];
    const float* W_sdc  = (const float*)d_in[1];
    const float* b_sdc  = (const float*)d_in[2];
    const float* w_syn  = (const float*)d_in[3];
    const float* W_pool = (const float*)d_in[4];
    const float* b_pool = (const float*)d_in[5];
    const float* W_f1   = (const float*)d_in[6];
    const float* b_f1   = (const float*)d_in[7];
    const float* W_f2   = (const float*)d_in[8];
    const float* b_f2   = (const float*)d_in[9];
    const float* W_out  = (const float*)d_in[10];
    const float* b_out  = (const float*)d_in[11];
    float* out = (float*)d_out;

    float* s2 = nullptr; float* h1 = nullptr; float* h2 = nullptr; float* part = nullptr;
    cudaGetSymbolAddress((void**)&s2, g_s2);
    cudaGetSymbolAddress((void**)&h1, g_h1);
    cudaGetSymbolAddress((void**)&h2, g_h2);
    cudaGetSymbolAddress((void**)&part, g_part);

    const int M = T_STEPS * N_BATCH;  // 512

    // K1: fused SNN core -> g_s2 [T,N,D]
    k_snn_core<<<N_BATCH * D_DIM, 256>>>(x, W_sdc, b_sdc, w_syn, W_pool, b_pool);

    // K2: partials of s2 @ W_f1  (M=512, K=256, N=512), S=4, Kc=64
    {
        dim3 grid(F1_DIM / 64, M / 32, 4);
        k_gemm_splitk<<<grid, 128>>>(s2, W_f1, part, M, D_DIM, F1_DIM, 64);
    }
    // K3: reduce(4) + bias + LIF -> h1
    k_reduce_lif<4><<<(N_BATCH * F1_DIM) / 256, 256>>>(part, b_f1, h1, F1_DIM);

    // K4: partials of h1 @ W_f2  (M=512, K=512, N=256), S=8, Kc=64
    {
        dim3 grid(F2_DIM / 64, M / 32, 8);
        k_gemm_splitk<<<grid, 128>>>(h1, W_f2, part, M, F1_DIM, F2_DIM, 64);
    }
    // K5: reduce(8) + bias + LIF -> h2
    k_reduce_lif<8><<<(N_BATCH * F2_DIM) / 256, 256>>>(part, b_f2, h2, F2_DIM);

    // K6: readout dot + cumsum
    k_head<<<N_BATCH, 256>>>(W_out, b_out, out);
}

// round 5
// speedup vs baseline: 1.0428x; 1.0428x over previous
#include <cuda_runtime.h>
#include <math.h>

#define T_STEPS 32
#define N_BATCH 16
#define D_DIM   256
#define A_DIM   256
#define F1_DIM  512
#define F2_DIM  256
#define BK 16

// Scratch (allocation-free rule: __device__ globals)
__device__ float g_s2[T_STEPS * N_BATCH * D_DIM];    // [T,N,D]   512KB
__device__ float g_h1[T_STEPS * N_BATCH * F1_DIM];   // [T,N,F1]  1MB
__device__ float g_h2[T_STEPS * N_BATCH * F2_DIM];   // [T,N,F2]  512KB
__device__ float g_part[9 * 256 * 1024];             // split-K partials, 9MB

// ---------------------------------------------------------------------------
// K1: fused SDC-linear + exp-filter + LIF + synapse-filter + pool + s2-LIF.
// warp = one (n,d); lane owns a = lane*8 .. lane*8+7.
// No shared memory, no __syncthreads. Pooled sum via shfl_xor butterfly
// (bit-identical on all lanes), LIF-2 chain run redundantly per lane,
// lane t keeps spike t -> one coalesced store per lane.
// ---------------------------------------------------------------------------
__global__ void __launch_bounds__(256) k_snn_core(
    const float* __restrict__ x,      // [T,N,2,D]
    const float* __restrict__ W_sdc,  // [2,A]
    const float* __restrict__ b_sdc,  // [A]
    const float* __restrict__ w_syn,  // [1]
    const float* __restrict__ W_pool, // [A,1]
    const float* __restrict__ b_pool) // [1]
{
    const int wid  = (blockIdx.x << 3) + (threadIdx.x >> 5);  // global warp
    const int lane = threadIdx.x & 31;
    const int n    = wid >> 8;     // D = 256
    const int d    = wid & 255;
    const int a0   = lane << 3;

    float w0[8], w1[8], ba[8], wp[8];
    *(float4*)(w0)     = *(const float4*)(W_sdc + a0);
    *(float4*)(w0 + 4) = *(const float4*)(W_sdc + a0 + 4);
    *(float4*)(w1)     = *(const float4*)(W_sdc + A_DIM + a0);
    *(float4*)(w1 + 4) = *(const float4*)(W_sdc + A_DIM + a0 + 4);
    *(float4*)(ba)     = *(const float4*)(b_sdc + a0);
    *(float4*)(ba + 4) = *(const float4*)(b_sdc + a0 + 4);
    *(float4*)(wp)     = *(const float4*)(W_pool + a0);
    *(float4*)(wp + 4) = *(const float4*)(W_pool + a0 + 4);

    const float dsyn = 1.0f - 1.0f / (1.0f + expf(-w_syn[0]));
    const float bp   = b_pool[0];

    float is[8], vv[8], sy[8];
    #pragma unroll
    for (int i = 0; i < 8; ++i) { is[i] = 0.0f; vv[i] = 0.0f; sy[i] = 0.0f; }

    float v2 = 0.0f, mys2 = 0.0f;
    const float* xp = x + n * 2 * D_DIM + d;   // step per t: N_BATCH*2*D_DIM

    #pragma unroll 4
    for (int t = 0; t < T_STEPS; ++t) {
        const float x0 = __ldg(xp);
        const float x1 = __ldg(xp + D_DIM);
        xp += N_BATCH * 2 * D_DIM;

        float sum = 0.0f;
        #pragma unroll
        for (int i = 0; i < 8; ++i) {
            const float h = fmaf(x0, w0[i], fmaf(x1, w1[i], ba[i]));
            is[i] = fmaf(is[i], 0.5f, h);                 // exp_filter tau=2
            vv[i] = fmaf(is[i] - vv[i], 0.5f, vv[i]);     // LIF tau=2
            const float s1 = (vv[i] >= 1.0f) ? 1.0f : 0.0f;
            vv[i] = (s1 != 0.0f) ? 0.0f : vv[i];
            sy[i] = fmaf(sy[i], dsyn, s1);                // synapse filter
            sum = fmaf(sy[i], wp[i], sum);
        }
        #pragma unroll
        for (int off = 16; off; off >>= 1)
            sum += __shfl_xor_sync(0xffffffffu, sum, off);
        sum += bp;

        // LIF-2 (identical on all lanes)
        v2 = fmaf(sum - v2, 0.5f, v2);
        const float s2v = (v2 >= 1.0f) ? 1.0f : 0.0f;
        v2 = (s2v != 0.0f) ? 0.0f : v2;
        if (lane == t) mys2 = s2v;
    }
    g_s2[(lane * N_BATCH + n) * D_DIM + d] = mys2;
}

// ---------------------------------------------------------------------------
// Split-K register-tiled SGEMM with global->register prefetch.
// P[s][M][N] partial = A[:,ks..ks+Kc] @ B slice. Tile 32x64, BK=16,
// 128 threads, 4x4 micro-tile. Deterministic.
// ---------------------------------------------------------------------------
__global__ void __launch_bounds__(128) k_gemm_splitk(
    const float* __restrict__ A, const float* __restrict__ B,
    float* __restrict__ P, int M, int K, int N, int Kc)
{
    __shared__ float As[BK][32];   // [k][m]
    __shared__ float Bs[BK][64];   // [k][n]
    const int tid = threadIdx.x;
    const int tx  = tid & 15;
    const int ty  = tid >> 4;
    const int row0 = blockIdx.y * 32;
    const int col0 = blockIdx.x * 64;
    const int kbeg = blockIdx.z * Kc;
    const int kend = kbeg + Kc;

    const int alr = tid >> 2;
    const int alk = (tid & 3) << 2;
    const int brr = tid >> 4;
    const int bcc = (tid & 15) << 2;

    float acc[4][4] = {};

    float4 av  = *(const float4*)(A + (row0 + alr) * K + kbeg + alk);
    float4 bv0 = *(const float4*)(B + (kbeg + brr    ) * N + col0 + bcc);
    float4 bv1 = *(const float4*)(B + (kbeg + brr + 8) * N + col0 + bcc);

    for (int k0 = kbeg; k0 < kend; k0 += BK) {
        As[alk + 0][alr] = av.x;
        As[alk + 1][alr] = av.y;
        As[alk + 2][alr] = av.z;
        As[alk + 3][alr] = av.w;
        *(float4*)(&Bs[brr][bcc])     = bv0;
        *(float4*)(&Bs[brr + 8][bcc]) = bv1;
        __syncthreads();

        const int kn = k0 + BK;
        if (kn < kend) {   // prefetch next tile while computing
            av  = *(const float4*)(A + (row0 + alr) * K + kn + alk);
            bv0 = *(const float4*)(B + (kn + brr    ) * N + col0 + bcc);
            bv1 = *(const float4*)(B + (kn + brr + 8) * N + col0 + bcc);
        }

        #pragma unroll
        for (int kk = 0; kk < BK; ++kk) {
            const float4 a = *(const float4*)(&As[kk][ty << 2]);
            const float4 b = *(const float4*)(&Bs[kk][tx << 2]);
            acc[0][0] = fmaf(a.x, b.x, acc[0][0]);
            acc[0][1] = fmaf(a.x, b.y, acc[0][1]);
            acc[0][2] = fmaf(a.x, b.z, acc[0][2]);
            acc[0][3] = fmaf(a.x, b.w, acc[0][3]);
            acc[1][0] = fmaf(a.y, b.x, acc[1][0]);
            acc[1][1] = fmaf(a.y, b.y, acc[1][1]);
            acc[1][2] = fmaf(a.y, b.z, acc[1][2]);
            acc[1][3] = fmaf(a.y, b.w, acc[1][3]);
            acc[2][0] = fmaf(a.z, b.x, acc[2][0]);
            acc[2][1] = fmaf(a.z, b.y, acc[2][1]);
            acc[2][2] = fmaf(a.z, b.z, acc[2][2]);
            acc[2][3] = fmaf(a.z, b.w, acc[2][3]);
            acc[3][0] = fmaf(a.w, b.x, acc[3][0]);
            acc[3][1] = fmaf(a.w, b.y, acc[3][1]);
            acc[3][2] = fmaf(a.w, b.z, acc[3][2]);
            acc[3][3] = fmaf(a.w, b.w, acc[3][3]);
        }
        __syncthreads();
    }

    float* Pout = P + blockIdx.z * M * N;
    #pragma unroll
    for (int i = 0; i < 4; ++i) {
        float4 o;
        o.x = acc[i][0]; o.y = acc[i][1]; o.z = acc[i][2]; o.w = acc[i][3];
        *(float4*)(Pout + (row0 + (ty << 2) + i) * N + col0 + (tx << 2)) = o;
    }
}

// ---------------------------------------------------------------------------
// Fused split-K reduce + bias + LIF scan over t.
// P[s][T*N_BATCH][F] partials -> out[T*N_BATCH][F] spikes. Deterministic.
// ---------------------------------------------------------------------------
template<int S>
__global__ void k_reduce_lif(const float* __restrict__ P,
                             const float* __restrict__ bias,
                             float* __restrict__ out, int F)
{
    const int j = blockIdx.x * blockDim.x + threadIdx.x;
    const int nb = j / F;
    const int f  = j % F;
    const int MN = T_STEPS * N_BATCH * F;
    const float b = bias[f];
    float v = 0.0f;
    #pragma unroll 4
    for (int t = 0; t < T_STEPS; ++t) {
        const int m = t * N_BATCH + nb;
        float val = b;
        #pragma unroll
        for (int s = 0; s < S; ++s) val += P[s * MN + m * F + f];
        v = fmaf(val - v, 0.5f, v);
        const float sp = (v >= 1.0f) ? 1.0f : 0.0f;
        out[m * F + f] = sp;
        v = (sp != 0.0f) ? 0.0f : v;
    }
}

// ---------------------------------------------------------------------------
// Head: o[t,n] = h2[t,n,:] . W_out + b_out ; out[t,n] = cumsum_t o
// ---------------------------------------------------------------------------
__global__ void __launch_bounds__(256) k_head(
    const float* __restrict__ W_out, const float* __restrict__ b_out,
    float* __restrict__ out)
{
    const int n = blockIdx.x;
    const int g = threadIdx.x;
    const int lane = g & 31;
    const int warp = g >> 5;
    const float w  = W_out[g];
    const float bo = b_out[0];
    __shared__ float sh[T_STEPS][8];

    #pragma unroll 4
    for (int t = 0; t < T_STEPS; ++t) {
        float val = g_h2[(t * N_BATCH + n) * F2_DIM + g] * w;
        #pragma unroll
        for (int off = 16; off; off >>= 1)
            val += __shfl_down_sync(0xffffffffu, val, off);
        if (lane == 0) sh[t][warp] = val;
    }
    __syncthreads();
    if (warp == 0) {
        float z = bo;
        #pragma unroll
        for (int w8 = 0; w8 < 8; ++w8) z += sh[lane][w8];
        float acc = 0.0f, mine = 0.0f;
        #pragma unroll
        for (int t = 0; t < T_STEPS; ++t) {
            acc += __shfl_sync(0xffffffffu, z, t);
            if (lane == t) mine = acc;
        }
        out[lane * N_BATCH + n] = mine;
    }
}

extern "C" void kernel_launch(void* const* d_in, const int* in_sizes, int n_in,
                              void* d_out, int out_size)
{
    const float* x      = (const float*)d_in[0];
    const float* W_sdc  = (const float*)d_in[1];
    const float* b_sdc  = (const float*)d_in[2];
    const float* w_syn  = (const float*)d_in[3];
    const float* W_pool = (const float*)d_in[4];
    const float* b_pool = (const float*)d_in[5];
    const float* W_f1   = (const float*)d_in[6];
    const float* b_f1   = (const float*)d_in[7];
    const float* W_f2   = (const float*)d_in[8];
    const float* b_f2   = (const float*)d_in[9];
    const float* W_out  = (const float*)d_in[10];
    const float* b_out  = (const float*)d_in[11];
    float* out = (float*)d_out;

    float* s2 = nullptr; float* h1 = nullptr; float* h2 = nullptr; float* part = nullptr;
    cudaGetSymbolAddress((void**)&s2, g_s2);
    cudaGetSymbolAddress((void**)&h1, g_h1);
    cudaGetSymbolAddress((void**)&h2, g_h2);
    cudaGetSymbolAddress((void**)&part, g_part);

    const int M = T_STEPS * N_BATCH;  // 512

    // K1: fused SNN core -> g_s2 [T,N,D].  512 blocks x 8 warps = 4096 warps.
    k_snn_core<<<(N_BATCH * D_DIM) / 8, 256>>>(x, W_sdc, b_sdc, w_syn, W_pool, b_pool);

    // K2: partials of s2 @ W_f1  (M=512, K=256, N=512), S=4, Kc=64 -> 512 blocks
    {
        dim3 grid(F1_DIM / 64, M / 32, 4);
        k_gemm_splitk<<<grid, 128>>>(s2, W_f1, part, M, D_DIM, F1_DIM, 64);
    }
    // K3: reduce(4) + bias + LIF -> h1
    k_reduce_lif<4><<<(N_BATCH * F1_DIM) / 256, 256>>>(part, b_f1, h1, F1_DIM);

    // K4: partials of h1 @ W_f2  (M=512, K=512, N=256), S=8, Kc=64 -> 512 blocks
    {
        dim3 grid(F2_DIM / 64, M / 32, 8);
        k_gemm_splitk<<<grid, 128>>>(h1, W_f2, part, M, F1_DIM, F2_DIM, 64);
    }
    // K5: reduce(8) + bias + LIF -> h2
    k_reduce_lif<8><<<(N_BATCH * F2_DIM) / 256, 256>>>(part, b_f2, h2, F2_DIM);

    // K6: readout dot + cumsum
    k_head<<<N_BATCH, 256>>>(W_out, b_out, out);
}

// round 6
// speedup vs baseline: 1.1889x; 1.1401x over previous
#include <cuda_runtime.h>
#include <math.h>

#define T_STEPS 32
#define N_BATCH 16
#define D_DIM   256
#define A_DIM   256
#define F1_DIM  512
#define F2_DIM  256
#define BK 16

// Scratch (allocation-free rule: __device__ globals)
__device__ float g_s2[T_STEPS * N_BATCH * D_DIM];    // [T,N,D]   512KB
__device__ float g_h1[T_STEPS * N_BATCH * F1_DIM];   // [T,N,F1]  1MB
__device__ float g_part[9 * 256 * 1024];             // split-K partials, 9MB

// ---------------------------------------------------------------------------
// K1: fused SDC-linear + exp-filter + LIF + synapse-filter + pool + s2-LIF.
// block = (n,d) (4096 blocks), thread = a (256). Lane owns ONE chain.
// Per-t: 5-shfl warp reduce -> sh[t][warp]. ONE barrier. Warp 0 epilogue.
// (R2 design: measured fastest variant of this kernel.)
// ---------------------------------------------------------------------------
__global__ void __launch_bounds__(256) k_snn_core(
    const float* __restrict__ x,      // [T,N,2,D]
    const float* __restrict__ W_sdc,  // [2,A]
    const float* __restrict__ b_sdc,  // [A]
    const float* __restrict__ w_syn,  // [1]
    const float* __restrict__ W_pool, // [A,1]
    const float* __restrict__ b_pool) // [1]
{
    const int a    = threadIdx.x;
    const int nd   = blockIdx.x;
    const int n    = nd >> 8;   // D = 256
    const int d    = nd & 255;
    const int lane = a & 31;
    const int warp = a >> 5;

    const float w0 = W_sdc[a];
    const float w1 = W_sdc[A_DIM + a];
    const float ba = b_sdc[a];
    const float wp = W_pool[a];
    const float dsyn = 1.0f - 1.0f / (1.0f + expf(-w_syn[0]));
    const float bp = b_pool[0];

    float i_s = 0.0f, v = 0.0f, syn = 0.0f;

    __shared__ float sh[T_STEPS][8];

    #pragma unroll 4
    for (int t = 0; t < T_STEPS; ++t) {
        const float x0 = x[((t * N_BATCH + n) * 2 + 0) * D_DIM + d];
        const float x1 = x[((t * N_BATCH + n) * 2 + 1) * D_DIM + d];
        const float h  = fmaf(x0, w0, fmaf(x1, w1, ba));

        i_s = fmaf(i_s, 0.5f, h);                     // exp_filter tau=2
        v = fmaf(i_s - v, 0.5f, v);                   // LIF tau=2
        const float s1 = (v >= 1.0f) ? 1.0f : 0.0f;
        v = (s1 != 0.0f) ? 0.0f : v;
        syn = fmaf(syn, dsyn, s1);                    // synapse filter

        float val = syn * wp;
        #pragma unroll
        for (int off = 16; off; off >>= 1)
            val += __shfl_down_sync(0xffffffffu, val, off);
        if (lane == 0) sh[t][warp] = val;
    }
    __syncthreads();

    if (warp == 0) {
        // lane == t
        float z = bp;
        #pragma unroll
        for (int w = 0; w < 8; ++w) z += sh[lane][w];

        float v2 = 0.0f, s_mine = 0.0f;
        #pragma unroll
        for (int t = 0; t < T_STEPS; ++t) {
            const float zt = __shfl_sync(0xffffffffu, z, t);
            v2 = fmaf(zt - v2, 0.5f, v2);
            const float s = (v2 >= 1.0f) ? 1.0f : 0.0f;
            v2 = (s != 0.0f) ? 0.0f : v2;
            if (lane == t) s_mine = s;
        }
        g_s2[(lane * N_BATCH + n) * D_DIM + d] = s_mine;
    }
}

// ---------------------------------------------------------------------------
// Split-K register-tiled SGEMM with global->register prefetch.
// P[s][M][N] partial = A[:,ks..ks+Kc] @ B slice. Tile 32x64, BK=16,
// 128 threads, 4x4 micro-tile. Deterministic.
// ---------------------------------------------------------------------------
__global__ void __launch_bounds__(128) k_gemm_splitk(
    const float* __restrict__ A, const float* __restrict__ B,
    float* __restrict__ P, int M, int K, int N, int Kc)
{
    __shared__ float As[BK][32];   // [k][m]
    __shared__ float Bs[BK][64];   // [k][n]
    const int tid = threadIdx.x;
    const int tx  = tid & 15;
    const int ty  = tid >> 4;
    const int row0 = blockIdx.y * 32;
    const int col0 = blockIdx.x * 64;
    const int kbeg = blockIdx.z * Kc;
    const int kend = kbeg + Kc;

    const int alr = tid >> 2;
    const int alk = (tid & 3) << 2;
    const int brr = tid >> 4;
    const int bcc = (tid & 15) << 2;

    float acc[4][4] = {};

    float4 av  = *(const float4*)(A + (row0 + alr) * K + kbeg + alk);
    float4 bv0 = *(const float4*)(B + (kbeg + brr    ) * N + col0 + bcc);
    float4 bv1 = *(const float4*)(B + (kbeg + brr + 8) * N + col0 + bcc);

    for (int k0 = kbeg; k0 < kend; k0 += BK) {
        As[alk + 0][alr] = av.x;
        As[alk + 1][alr] = av.y;
        As[alk + 2][alr] = av.z;
        As[alk + 3][alr] = av.w;
        *(float4*)(&Bs[brr][bcc])     = bv0;
        *(float4*)(&Bs[brr + 8][bcc]) = bv1;
        __syncthreads();

        const int kn = k0 + BK;
        if (kn < kend) {   // prefetch next tile while computing
            av  = *(const float4*)(A + (row0 + alr) * K + kn + alk);
            bv0 = *(const float4*)(B + (kn + brr    ) * N + col0 + bcc);
            bv1 = *(const float4*)(B + (kn + brr + 8) * N + col0 + bcc);
        }

        #pragma unroll
        for (int kk = 0; kk < BK; ++kk) {
            const float4 a = *(const float4*)(&As[kk][ty << 2]);
            const float4 b = *(const float4*)(&Bs[kk][tx << 2]);
            acc[0][0] = fmaf(a.x, b.x, acc[0][0]);
            acc[0][1] = fmaf(a.x, b.y, acc[0][1]);
            acc[0][2] = fmaf(a.x, b.z, acc[0][2]);
            acc[0][3] = fmaf(a.x, b.w, acc[0][3]);
            acc[1][0] = fmaf(a.y, b.x, acc[1][0]);
            acc[1][1] = fmaf(a.y, b.y, acc[1][1]);
            acc[1][2] = fmaf(a.y, b.z, acc[1][2]);
            acc[1][3] = fmaf(a.y, b.w, acc[1][3]);
            acc[2][0] = fmaf(a.z, b.x, acc[2][0]);
            acc[2][1] = fmaf(a.z, b.y, acc[2][1]);
            acc[2][2] = fmaf(a.z, b.z, acc[2][2]);
            acc[2][3] = fmaf(a.z, b.w, acc[2][3]);
            acc[3][0] = fmaf(a.w, b.x, acc[3][0]);
            acc[3][1] = fmaf(a.w, b.y, acc[3][1]);
            acc[3][2] = fmaf(a.w, b.z, acc[3][2]);
            acc[3][3] = fmaf(a.w, b.w, acc[3][3]);
        }
        __syncthreads();
    }

    float* Pout = P + blockIdx.z * M * N;
    #pragma unroll
    for (int i = 0; i < 4; ++i) {
        float4 o;
        o.x = acc[i][0]; o.y = acc[i][1]; o.z = acc[i][2]; o.w = acc[i][3];
        *(float4*)(Pout + (row0 + (ty << 2) + i) * N + col0 + (tx << 2)) = o;
    }
}

// ---------------------------------------------------------------------------
// Fused split-K reduce + bias + LIF scan over t.
// P[s][T*N_BATCH][F] partials -> out[T*N_BATCH][F] spikes. Deterministic.
// ---------------------------------------------------------------------------
template<int S>
__global__ void k_reduce_lif(const float* __restrict__ P,
                             const float* __restrict__ bias,
                             float* __restrict__ out, int F)
{
    const int j = blockIdx.x * blockDim.x + threadIdx.x;
    const int nb = j / F;
    const int f  = j % F;
    const int MN = T_STEPS * N_BATCH * F;
    const float b = bias[f];
    float v = 0.0f;
    #pragma unroll 4
    for (int t = 0; t < T_STEPS; ++t) {
        const int m = t * N_BATCH + nb;
        float val = b;
        #pragma unroll
        for (int s = 0; s < S; ++s) val += P[s * MN + m * F + f];
        v = fmaf(val - v, 0.5f, v);
        const float sp = (v >= 1.0f) ? 1.0f : 0.0f;
        out[m * F + f] = sp;
        v = (sp != 0.0f) ? 0.0f : v;
    }
}

// ---------------------------------------------------------------------------
// K5: fused reduce(8) + bias + LIF + W_out dot + cumsum -> final output.
// block = nb (16 blocks), thread = f2 (256). Per-t warp reduce into sh[t][warp],
// one barrier, warp-0 cumsum epilogue. Deterministic (fixed order).
// ---------------------------------------------------------------------------
__global__ void __launch_bounds__(256) k_tail(
    const float* __restrict__ P,      // [8][T*N][F2] partials
    const float* __restrict__ bias,   // b_f2
    const float* __restrict__ W_out,  // [F2]
    const float* __restrict__ b_out,  // [1]
    float* __restrict__ out)          // [T,N]
{
    const int nb   = blockIdx.x;
    const int f    = threadIdx.x;
    const int lane = f & 31;
    const int warp = f >> 5;
    const int MN   = T_STEPS * N_BATCH * F2_DIM;

    const float b  = bias[f];
    const float w  = W_out[f];
    const float bo = b_out[0];

    __shared__ float sh[T_STEPS][8];
    float v = 0.0f;

    #pragma unroll 4
    for (int t = 0; t < T_STEPS; ++t) {
        const int m = t * N_BATCH + nb;
        float val = b;
        #pragma unroll
        for (int s = 0; s < 8; ++s) val += P[s * MN + m * F2_DIM + f];
        v = fmaf(val - v, 0.5f, v);
        const float sp = (v >= 1.0f) ? 1.0f : 0.0f;
        v = (sp != 0.0f) ? 0.0f : v;

        float r = sp * w;
        #pragma unroll
        for (int off = 16; off; off >>= 1)
            r += __shfl_down_sync(0xffffffffu, r, off);
        if (lane == 0) sh[t][warp] = r;
    }
    __syncthreads();

    if (warp == 0) {
        float z = bo;
        #pragma unroll
        for (int w8 = 0; w8 < 8; ++w8) z += sh[lane][w8];
        float acc = 0.0f, mine = 0.0f;
        #pragma unroll
        for (int t = 0; t < T_STEPS; ++t) {
            acc += __shfl_sync(0xffffffffu, z, t);
            if (lane == t) mine = acc;
        }
        out[lane * N_BATCH + nb] = mine;
    }
}

extern "C" void kernel_launch(void* const* d_in, const int* in_sizes, int n_in,
                              void* d_out, int out_size)
{
    const float* x      = (const float*)d_in[0];
    const float* W_sdc  = (const float*)d_in[1];
    const float* b_sdc  = (const float*)d_in[2];
    const float* w_syn  = (const float*)d_in[3];
    const float* W_pool = (const float*)d_in[4];
    const float* b_pool = (const float*)d_in[5];
    const float* W_f1   = (const float*)d_in[6];
    const float* b_f1   = (const float*)d_in[7];
    const float* W_f2   = (const float*)d_in[8];
    const float* b_f2   = (const float*)d_in[9];
    const float* W_out  = (const float*)d_in[10];
    const float* b_out  = (const float*)d_in[11];
    float* out = (float*)d_out;

    float* s2 = nullptr; float* h1 = nullptr; float* part = nullptr;
    cudaGetSymbolAddress((void**)&s2, g_s2);
    cudaGetSymbolAddress((void**)&h1, g_h1);
    cudaGetSymbolAddress((void**)&part, g_part);

    const int M = T_STEPS * N_BATCH;  // 512

    // K1: fused SNN core -> g_s2 [T,N,D]
    k_snn_core<<<N_BATCH * D_DIM, 256>>>(x, W_sdc, b_sdc, w_syn, W_pool, b_pool);

    // K2: partials of s2 @ W_f1  (M=512, K=256, N=512), S=4, Kc=64 -> 512 blocks
    {
        dim3 grid(F1_DIM / 64, M / 32, 4);
        k_gemm_splitk<<<grid, 128>>>(s2, W_f1, part, M, D_DIM, F1_DIM, 64);
    }
    // K3: reduce(4) + bias + LIF -> h1
    k_reduce_lif<4><<<(N_BATCH * F1_DIM) / 256, 256>>>(part, b_f1, h1, F1_DIM);

    // K4: partials of h1 @ W_f2  (M=512, K=512, N=256), S=8, Kc=64 -> 512 blocks
    {
        dim3 grid(F2_DIM / 64, M / 32, 8);
        k_gemm_splitk<<<grid, 128>>>(h1, W_f2, part, M, F1_DIM, F2_DIM, 64);
    }
    // K5: fused reduce(8) + LIF + readout dot + cumsum -> out
    k_tail<<<N_BATCH, 256>>>(part, b_f2, W_out, b_out, out);
}